// round 13
// baseline (speedup 1.0000x reference)
#include <cuda_runtime.h>
#include <cstdint>

#define NPOS   1296
#define NPOSX  36
#define BCN    32
#define HW     160
#define SLOT   52                       // floats per (pos,n) record: 49 den + pad
#define STEPS  (NPOS*10)                // 12960 updates per plane (chronological)
#define LUTN   2048
#define SC_SMEM (STEPS*4 + LUTN*4)      // coords + reciprocal LUT = 60,032 B

__device__ float    g_den[(size_t)BCN*NPOS*10*SLOT + 4096];
__device__ unsigned g_coords[(size_t)BCN*STEPS];
__device__ float    g_M[49*49];
__device__ float    g_b2[10*49];

// ---------------- Kernel P: fuse the two linear layers ----------------
__global__ void __launch_bounds__(256) kprep(const float* __restrict__ Wp, const float* __restrict__ bp,
                      const float* __restrict__ pe, const float* __restrict__ Wb,
                      const float* __restrict__ bb) {
    int t = blockIdx.x * blockDim.x + threadIdx.x;
    int stride = gridDim.x * blockDim.x;
    for (int idx = t; idx < 49*49; idx += stride) {
        int k = idx/49, j = idx%49;
        float a = 0.f;
        for (int e = 0; e < 128; e++) a = fmaf(Wp[k*128+e], Wb[e*49+j], a);
        g_M[idx] = a;
    }
    for (int idx = t; idx < 10*49; idx += stride) {
        int n = idx/49, j = idx%49;
        float a = bb[j];
        for (int e = 0; e < 128; e++) a = fmaf(bp[e] + pe[n*128+e], Wb[e*49+j], a);
        g_b2[idx] = a;
    }
}

// ---------------- Kernel A: sim + exact top-10 + fused projection (R7 known-good) ----------------
__global__ void __launch_bounds__(256, 6) kmain(const float* __restrict__ images) {
    __shared__ float win[400];
    __shared__ float ref[49];
    __shared__ float Ms[49*49];
    __shared__ float b2s[10*49];
    __shared__ unsigned long long keys[224];
    __shared__ unsigned widx[10];

    int t   = threadIdx.x;
    int blk = blockIdx.x;
    int p   = blk >> 5;          // position index (x-outer, y-inner)
    int bc  = blk & 31;
    int xidx = p / NPOSX, yidx = p % NPOSX;
    int x = 4*xidx, y = 4*yidx;
    int xb0 = max(x-7, 0), yb0 = max(y-7, 0);
    int jmax = (x + 13 - xb0) - 7;
    int imax = (y + 13 - yb0) - 7;

    const float* ip = images + (size_t)bc*HW*HW;
    for (int idx = t; idx < 400; idx += 256)
        win[idx] = ip[(yb0 + idx/20)*HW + xb0 + idx%20];
    if (t < 49)  ref[t] = ip[(y + t/7)*HW + x + t%7];
    __syncthreads();

    unsigned long long key = 0ull;
    if (t < 196) {
        int i = t/14, j = t%14;
        if (i <= imax && j <= jmax) {
            float s = 0.f;
            #pragma unroll
            for (int u = 0; u < 7; u++)
                #pragma unroll
                for (int v = 0; v < 7; v++)
                    s = fmaf(win[(i+u)*20 + j+v], ref[u*7+v], s);
            unsigned b   = __float_as_uint(s);
            unsigned ord = (b & 0x80000000u) ? ~b : (b | 0x80000000u);
            key = ((unsigned long long)ord << 32) | (unsigned)(1023 - t);  // ties -> smaller index
        }
    }
    if (t < 224) keys[t] = key;
    __syncthreads();

    int lane = t & 31, wid = t >> 5;
    if (wid == 0) {
        unsigned long long kk[7];
        #pragma unroll
        for (int s = 0; s < 7; s++) kk[s] = keys[lane + 32*s];
        #pragma unroll
        for (int r = 0; r < 10; r++) {
            unsigned long long m = kk[0];
            #pragma unroll
            for (int s = 1; s < 7; s++) if (kk[s] > m) m = kk[s];
            #pragma unroll
            for (int off = 16; off; off >>= 1) {
                unsigned long long o = __shfl_xor_sync(0xFFFFFFFFu, m, off);
                if (o > m) m = o;
            }
            if (lane == 0) widx[r] = 1023u - (unsigned)(m & 0xFFFFFFFFull);
            #pragma unroll
            for (int s = 0; s < 7; s++) if (kk[s] == m) kk[s] = 0ull;
        }
    } else {
        for (int idx = t - 32; idx < 49*49; idx += 224) Ms[idx] = g_M[idx];
        for (int idx = t - 32; idx < 490;   idx += 224) b2s[idx] = g_b2[idx];
    }
    __syncthreads();

    size_t base0 = (((size_t)bc*NPOS + p)*10)*SLOT;
    #pragma unroll
    for (int base = 0; base < 490; base += 256) {
        int tt = base + t;
        if (tt < 490) {
            int n = tt/49, j = tt%49;
            unsigned w = widx[n];
            int oy = w/14, ox = w%14;
            float acc = b2s[n*49 + j];
            #pragma unroll
            for (int kc = 0; kc < 7; kc++)
                #pragma unroll
                for (int kr = 0; kr < 7; kr++)
                    acc = fmaf(win[(oy+kr)*20 + ox+kc], Ms[(kc*7+kr)*49 + j], acc);
            g_den[base0 + n*SLOT + j] = acc;
        }
    }
    if (t < 10) {
        unsigned w = widx[t];
        int oy = w/14, ox = w%14;
        unsigned xi = (unsigned)(oy + xb0);   // source's coordinate swap kept
        unsigned yi = (unsigned)(ox + yb0);
        g_coords[(size_t)bc*STEPS + p*10 + t] = xi | (yi << 8);
    }
}

// ---------------- Kernel C2: per-cell affine-fold scatter (fully parallel) ----------------
// Update at cell: v' = (v*c + d)/(c+1) = a*v + b, a=c/(c+1), b=d/(c+1),
// c = 1 + (#increment events at cell from strictly earlier steps).
// One warp per (plane,row); lane owns cells col = lane + 32*m, m=0..4.
// Read slice of step (xi,yi): rows yi..yi+6, cols xi..xi+6, d = den[step][u*7+v].
// Inc  slice (transposed):    rows xi..xi+6, cols yi..yi+6.
__global__ void __launch_bounds__(256) kscatter2(const float* __restrict__ images,
                                                 float* __restrict__ out) {
    extern __shared__ unsigned sm_u[];
    unsigned* coords = sm_u;                         // [STEPS]
    float*    lut    = (float*)(sm_u + STEPS);       // [LUTN]: 1/k

    int plane = blockIdx.x;
    int tid = threadIdx.x, lane = tid & 31, wid = tid >> 5;
    int r = blockIdx.y * 8 + wid;                    // owned row

    const unsigned* gc = g_coords + (size_t)plane*STEPS;
    for (int i = tid; i < STEPS; i += 256) coords[i] = gc[i];
    for (int k = tid; k < LUTN; k += 256) lut[k] = (k == 0) ? 0.f : 1.0f/(float)k;
    __syncthreads();

    const float* denp = g_den + (size_t)plane * ((size_t)STEPS*SLOT);

    float A[5] = {1.f,1.f,1.f,1.f,1.f};
    float B[5] = {0.f,0.f,0.f,0.f,0.f};
    int   n[5] = {0,0,0,0,0};

    for (int base = 0; base < STEPS; base += 32) {
        unsigned cv = coords[base + lane];
        int xi = (int)(cv & 255u), yi = (int)((cv >> 8) & 255u);
        bool rel = ((unsigned)(r - yi) <= 6u) | ((unsigned)(r - xi) <= 6u);
        unsigned mask = __ballot_sync(0xFFFFFFFFu, rel);
        while (mask) {
            int b = __ffs(mask) - 1; mask &= mask - 1;
            unsigned ce = __shfl_sync(0xFFFFFFFFu, cv, b);
            int xe = (int)(ce & 255u), ye = (int)((ce >> 8) & 255u);
            // read part first (uses pre-step count)
            int u = r - ye;
            if ((unsigned)u <= 6u) {
                int tt = (lane - xe) & 31;
                if (tt <= 6) {
                    int m = ((xe + tt) - lane) >> 5;       // 0..4
                    float d = __ldg(denp + (size_t)(base + b)*SLOT + u*7 + tt);
                    #pragma unroll
                    for (int mm = 0; mm < 5; mm++) if (m == mm) {
                        int nn = n[mm];
                        float inv = (nn + 2 < LUTN) ? lut[nn + 2]
                                                    : __fdividef(1.f, (float)(nn + 2));
                        float a = (float)(nn + 1) * inv;   // c/(c+1), c = nn+1
                        A[mm] *= a;
                        B[mm] = fmaf(B[mm], a, d * inv);
                    }
                }
            }
            // increment part (transposed slice)
            int u2 = r - xe;
            if ((unsigned)u2 <= 6u) {
                int t2 = (lane - ye) & 31;
                if (t2 <= 6) {
                    int m2 = ((ye + t2) - lane) >> 5;
                    #pragma unroll
                    for (int mm = 0; mm < 5; mm++) if (m2 == mm) n[mm]++;
                }
            }
        }
    }

    const float* src = images + (size_t)plane*HW*HW;
    float*       op  = out    + (size_t)plane*HW*HW;
    #pragma unroll
    for (int mm = 0; mm < 5; mm++) {
        int c = lane + 32*mm;
        float v0 = src[r*HW + c];
        op[r*HW + c] = fmaf(A[mm], v0, B[mm]);
    }
}

extern "C" void kernel_launch(void* const* d_in, const int* in_sizes, int n_in,
                              void* d_out, int out_size) {
    const float* images = (const float*)d_in[0];
    const float* Wp     = (const float*)d_in[1];
    const float* bp     = (const float*)d_in[2];
    const float* pe     = (const float*)d_in[3];
    const float* Wb     = (const float*)d_in[4];
    const float* bb     = (const float*)d_in[5];
    float* out = (float*)d_out;

    cudaFuncSetAttribute(kscatter2, cudaFuncAttributeMaxDynamicSharedMemorySize, SC_SMEM);

    kprep<<<12, 256>>>(Wp, bp, pe, Wb, bb);
    kmain<<<NPOS*BCN, 256>>>(images);
    kscatter2<<<dim3(BCN, 20), 256, SC_SMEM>>>(images, out);
}

// round 16
// speedup vs baseline: 1.5974x; 1.5974x over previous
#include <cuda_runtime.h>
#include <cstdint>

#define NPOS   1296
#define NPOSX  36
#define BCN    32
#define HW     160
#define SLOT   52                       // floats per (pos,n) record: 49 den + pad
#define STEPS  (NPOS*10)                // 12960 updates per plane (chronological)
#define LUTN   2048
#define SC_SMEM (STEPS*4 + LUTN*4)      // coords + reciprocal LUT = 60,032 B

__device__ float    g_den[(size_t)BCN*NPOS*10*SLOT + 4096];
__device__ unsigned g_coords[(size_t)BCN*STEPS];
__device__ float    g_M[49*49];
__device__ float    g_b2[10*49];

// ---------------- Kernel P: fuse the two linear layers ----------------
__global__ void __launch_bounds__(256) kprep(const float* __restrict__ Wp, const float* __restrict__ bp,
                      const float* __restrict__ pe, const float* __restrict__ Wb,
                      const float* __restrict__ bb) {
    int t = blockIdx.x * blockDim.x + threadIdx.x;
    int stride = gridDim.x * blockDim.x;
    for (int idx = t; idx < 49*49; idx += stride) {
        int k = idx/49, j = idx%49;
        float a = 0.f;
        for (int e = 0; e < 128; e++) a = fmaf(Wp[k*128+e], Wb[e*49+j], a);
        g_M[idx] = a;
    }
    for (int idx = t; idx < 10*49; idx += stride) {
        int n = idx/49, j = idx%49;
        float a = bb[j];
        for (int e = 0; e < 128; e++) a = fmaf(bp[e] + pe[n*128+e], Wb[e*49+j], a);
        g_b2[idx] = a;
    }
}

// ---------------- Kernel A: sim + exact top-10 + fused projection (R7 known-good) ----------------
__global__ void __launch_bounds__(256, 6) kmain(const float* __restrict__ images) {
    __shared__ float win[400];
    __shared__ float ref[49];
    __shared__ float Ms[49*49];
    __shared__ float b2s[10*49];
    __shared__ unsigned long long keys[224];
    __shared__ unsigned widx[10];

    int t   = threadIdx.x;
    int blk = blockIdx.x;
    int p   = blk >> 5;          // position index (x-outer, y-inner)
    int bc  = blk & 31;
    int xidx = p / NPOSX, yidx = p % NPOSX;
    int x = 4*xidx, y = 4*yidx;
    int xb0 = max(x-7, 0), yb0 = max(y-7, 0);
    int jmax = (x + 13 - xb0) - 7;
    int imax = (y + 13 - yb0) - 7;

    const float* ip = images + (size_t)bc*HW*HW;
    for (int idx = t; idx < 400; idx += 256)
        win[idx] = ip[(yb0 + idx/20)*HW + xb0 + idx%20];
    if (t < 49)  ref[t] = ip[(y + t/7)*HW + x + t%7];
    __syncthreads();

    unsigned long long key = 0ull;
    if (t < 196) {
        int i = t/14, j = t%14;
        if (i <= imax && j <= jmax) {
            float s = 0.f;
            #pragma unroll
            for (int u = 0; u < 7; u++)
                #pragma unroll
                for (int v = 0; v < 7; v++)
                    s = fmaf(win[(i+u)*20 + j+v], ref[u*7+v], s);
            unsigned b   = __float_as_uint(s);
            unsigned ord = (b & 0x80000000u) ? ~b : (b | 0x80000000u);
            key = ((unsigned long long)ord << 32) | (unsigned)(1023 - t);  // ties -> smaller index
        }
    }
    if (t < 224) keys[t] = key;
    __syncthreads();

    int lane = t & 31, wid = t >> 5;
    if (wid == 0) {
        unsigned long long kk[7];
        #pragma unroll
        for (int s = 0; s < 7; s++) kk[s] = keys[lane + 32*s];
        #pragma unroll
        for (int r = 0; r < 10; r++) {
            unsigned long long m = kk[0];
            #pragma unroll
            for (int s = 1; s < 7; s++) if (kk[s] > m) m = kk[s];
            #pragma unroll
            for (int off = 16; off; off >>= 1) {
                unsigned long long o = __shfl_xor_sync(0xFFFFFFFFu, m, off);
                if (o > m) m = o;
            }
            if (lane == 0) widx[r] = 1023u - (unsigned)(m & 0xFFFFFFFFull);
            #pragma unroll
            for (int s = 0; s < 7; s++) if (kk[s] == m) kk[s] = 0ull;
        }
    } else {
        for (int idx = t - 32; idx < 49*49; idx += 224) Ms[idx] = g_M[idx];
        for (int idx = t - 32; idx < 490;   idx += 224) b2s[idx] = g_b2[idx];
    }
    __syncthreads();

    size_t base0 = (((size_t)bc*NPOS + p)*10)*SLOT;
    #pragma unroll
    for (int base = 0; base < 490; base += 256) {
        int tt = base + t;
        if (tt < 490) {
            int n = tt/49, j = tt%49;
            unsigned w = widx[n];
            int oy = w/14, ox = w%14;
            float acc = b2s[n*49 + j];
            #pragma unroll
            for (int kc = 0; kc < 7; kc++)
                #pragma unroll
                for (int kr = 0; kr < 7; kr++)
                    acc = fmaf(win[(oy+kr)*20 + ox+kc], Ms[(kc*7+kr)*49 + j], acc);
            g_den[base0 + n*SLOT + j] = acc;
        }
    }
    if (t < 10) {
        unsigned w = widx[t];
        int oy = w/14, ox = w%14;
        unsigned xi = (unsigned)(oy + xb0);   // source's coordinate swap kept
        unsigned yi = (unsigned)(ox + yb0);
        g_coords[(size_t)bc*STEPS + p*10 + t] = xi | (yi << 8);
    }
}

// ---------------- Kernel C2: per-cell affine-fold scatter (fully parallel) ----------------
// Update at cell: v' = (v*c + d)/(c+1) = a*v + b, a=c/(c+1), b=d/(c+1),
// c = 1 + (#increment events at cell from strictly earlier steps).
// One warp per (plane,row); lane owns cells col = lane + 32*m, m=0..4.
// Read slice of step (xi,yi): rows yi..yi+6, cols xi..xi+6, d = den[step][u*7+v].
// Inc  slice (transposed):    rows xi..xi+6, cols yi..yi+6.
__global__ void __launch_bounds__(256) kscatter2(const float* __restrict__ images,
                                                 float* __restrict__ out) {
    extern __shared__ unsigned sm_u[];
    unsigned* coords = sm_u;                         // [STEPS]
    float*    lut    = (float*)(sm_u + STEPS);       // [LUTN]: 1/k

    int plane = blockIdx.x;
    int tid = threadIdx.x, lane = tid & 31, wid = tid >> 5;
    int r = blockIdx.y * 8 + wid;                    // owned row

    const unsigned* gc = g_coords + (size_t)plane*STEPS;
    for (int i = tid; i < STEPS; i += 256) coords[i] = gc[i];
    for (int k = tid; k < LUTN; k += 256) lut[k] = (k == 0) ? 0.f : 1.0f/(float)k;
    __syncthreads();

    const float* denp = g_den + (size_t)plane * ((size_t)STEPS*SLOT);

    float A[5] = {1.f,1.f,1.f,1.f,1.f};
    float B[5] = {0.f,0.f,0.f,0.f,0.f};
    int   n[5] = {0,0,0,0,0};

    for (int base = 0; base < STEPS; base += 32) {
        unsigned cv = coords[base + lane];
        int xi = (int)(cv & 255u), yi = (int)((cv >> 8) & 255u);
        bool rel = ((unsigned)(r - yi) <= 6u) | ((unsigned)(r - xi) <= 6u);
        unsigned mask = __ballot_sync(0xFFFFFFFFu, rel);
        while (mask) {
            int b = __ffs(mask) - 1; mask &= mask - 1;
            unsigned ce = __shfl_sync(0xFFFFFFFFu, cv, b);
            int xe = (int)(ce & 255u), ye = (int)((ce >> 8) & 255u);
            // read part first (uses pre-step count)
            int u = r - ye;
            if ((unsigned)u <= 6u) {
                int tt = (lane - xe) & 31;
                if (tt <= 6) {
                    int m = ((xe + tt) - lane) >> 5;       // 0..4
                    float d = __ldg(denp + (size_t)(base + b)*SLOT + u*7 + tt);
                    #pragma unroll
                    for (int mm = 0; mm < 5; mm++) if (m == mm) {
                        int nn = n[mm];
                        float inv = (nn + 2 < LUTN) ? lut[nn + 2]
                                                    : __fdividef(1.f, (float)(nn + 2));
                        float a = (float)(nn + 1) * inv;   // c/(c+1), c = nn+1
                        A[mm] *= a;
                        B[mm] = fmaf(B[mm], a, d * inv);
                    }
                }
            }
            // increment part (transposed slice)
            int u2 = r - xe;
            if ((unsigned)u2 <= 6u) {
                int t2 = (lane - ye) & 31;
                if (t2 <= 6) {
                    int m2 = ((ye + t2) - lane) >> 5;
                    #pragma unroll
                    for (int mm = 0; mm < 5; mm++) if (m2 == mm) n[mm]++;
                }
            }
        }
    }

    const float* src = images + (size_t)plane*HW*HW;
    float*       op  = out    + (size_t)plane*HW*HW;
    #pragma unroll
    for (int mm = 0; mm < 5; mm++) {
        int c = lane + 32*mm;
        float v0 = src[r*HW + c];
        op[r*HW + c] = fmaf(A[mm], v0, B[mm]);
    }
}

extern "C" void kernel_launch(void* const* d_in, const int* in_sizes, int n_in,
                              void* d_out, int out_size) {
    const float* images = (const float*)d_in[0];
    const float* Wp     = (const float*)d_in[1];
    const float* bp     = (const float*)d_in[2];
    const float* pe     = (const float*)d_in[3];
    const float* Wb     = (const float*)d_in[4];
    const float* bb     = (const float*)d_in[5];
    float* out = (float*)d_out;

    cudaFuncSetAttribute(kscatter2, cudaFuncAttributeMaxDynamicSharedMemorySize, SC_SMEM);

    kprep<<<12, 256>>>(Wp, bp, pe, Wb, bb);
    kmain<<<NPOS*BCN, 256>>>(images);
    kscatter2<<<dim3(BCN, 20), 256, SC_SMEM>>>(images, out);
}